// round 12
// baseline (speedup 1.0000x reference)
#include <cuda_runtime.h>
#include <cuda_fp16.h>
#include <cstddef>

#define NN_MAX 50000
#define EE_MAX 1600000
#define SCAN_B 1024
#define NB_MAX 64

// -------- scratch (device globals; no allocation allowed) --------
__device__ __align__(16) float  g_dis[NN_MAX];
__device__ int    g_cnt[NN_MAX];
__device__ int    g_off[NN_MAX + 1];
__device__ int    g_sl[NN_MAX];
__device__ int    g_bsum[NB_MAX];
__device__ __align__(16) int g_slot[EE_MAX];
__device__ __align__(16) int g_csr[EE_MAX];
__device__ __align__(16) __half g_h16[(size_t)NN_MAX * 128];  // post-GEMM, pre-scaled
__device__ __align__(16) __half g_a16[(size_t)NN_MAX * 128];  // post-agg activations
__device__ float  g_t[NN_MAX];

// ---------------- helpers ----------------
__device__ __forceinline__ float4 h8_to_f4(float2 raw) {
    __half2 ha = *reinterpret_cast<__half2*>(&raw.x);
    __half2 hb = *reinterpret_cast<__half2*>(&raw.y);
    float2 fa = __half22float2(ha), fb = __half22float2(hb);
    return make_float4(fa.x, fa.y, fb.x, fb.y);
}
__device__ __forceinline__ float2 f4_to_h8(float x, float y, float z, float w) {
    __half2 h0 = __floats2half2_rn(x, y), h1 = __floats2half2_rn(z, w);
    float2 o;
    o.x = *reinterpret_cast<float*>(&h0);
    o.y = *reinterpret_cast<float*>(&h1);
    return o;
}
__device__ __forceinline__ float4 pairsum_f4(float2 ra, float2 rb) {
    __half2 alo = *reinterpret_cast<__half2*>(&ra.x);
    __half2 ahi = *reinterpret_cast<__half2*>(&ra.y);
    __half2 blo = *reinterpret_cast<__half2*>(&rb.x);
    __half2 bhi = *reinterpret_cast<__half2*>(&rb.y);
    __half2 slo = __hadd2(alo, blo);
    __half2 shi = __hadd2(ahi, bhi);
    float2 fa = __half22float2(slo), fb = __half22float2(shi);
    return make_float4(fa.x, fa.y, fb.x, fb.y);
}

// ---------------- graph preprocessing ----------------
__global__ void zero_cnt_k(int n) {
    int i = blockIdx.x * blockDim.x + threadIdx.x;
    if (i < n) g_cnt[i] = 0;
}

__global__ void hist_dst_k(const int* __restrict__ ei, int E) {
    int t = blockIdx.x * blockDim.x + threadIdx.x;
    int e = t * 4;
    if (e + 3 < E) {
        int4 d = *(const int4*)(ei + E + e);
        int p0 = atomicAdd(&g_cnt[d.x], 1);
        int p1 = atomicAdd(&g_cnt[d.y], 1);
        int p2 = atomicAdd(&g_cnt[d.z], 1);
        int p3 = atomicAdd(&g_cnt[d.w], 1);
        *(int4*)(g_slot + e) = make_int4(p0, p1, p2, p3);
    } else {
        for (; e < E; e++) g_slot[e] = atomicAdd(&g_cnt[ei[E + e]], 1);
    }
}

// dis for agg kernels (off critical path; GEMM computes rsqrt from g_cnt itself)
__global__ void dis_k(int n) {
    int i = blockIdx.x * blockDim.x + threadIdx.x;
    if (i < n) g_dis[i] = rsqrtf(1.0f + (float)g_cnt[i]);
}

__global__ void scan1_k(int n) {
    __shared__ int sh[SCAN_B];
    int t = threadIdx.x;
    int i = blockIdx.x * SCAN_B + t;
    int v = (i < n) ? g_cnt[i] : 0;
    sh[t] = v;
    __syncthreads();
    for (int d = 1; d < SCAN_B; d <<= 1) {
        int u = (t >= d) ? sh[t - d] : 0;
        __syncthreads();
        sh[t] += u;
        __syncthreads();
    }
    if (i < n) g_sl[i] = sh[t] - v;
    if (t == SCAN_B - 1) g_bsum[blockIdx.x] = sh[t];
}

__global__ void scan3_k(int n, int nb) {
    __shared__ int sh[NB_MAX];
    int t = threadIdx.x;
    if (t < NB_MAX) sh[t] = (t < nb) ? g_bsum[t] : 0;
    __syncthreads();
    for (int d = 1; d < NB_MAX; d <<= 1) {
        int u = (t < NB_MAX && t >= d) ? sh[t - d] : 0;
        __syncthreads();
        if (t < NB_MAX) sh[t] += u;
        __syncthreads();
    }
    int i = blockIdx.x * blockDim.x + t;
    if (i >= n) return;
    int bidx = i >> 10;
    int boff = (bidx > 0) ? sh[bidx - 1] : 0;
    int off = g_sl[i] + boff;
    g_off[i] = off;
    if (i == n - 1) g_off[n] = off + g_cnt[i];
}

__global__ void build_csr_k(const int* __restrict__ ei, int E) {
    int t = blockIdx.x * blockDim.x + threadIdx.x;
    int e = t * 4;
    if (e + 3 < E) {
        int4 s  = *(const int4*)(ei + e);
        int4 d  = *(const int4*)(ei + E + e);
        int4 sl = *(const int4*)(g_slot + e);
        g_csr[g_off[d.x] + sl.x] = s.x;
        g_csr[g_off[d.y] + sl.y] = s.y;
        g_csr[g_off[d.z] + sl.z] = s.z;
        g_csr[g_off[d.w] + sl.w] = s.w;
    } else {
        for (; e < E; e++) g_csr[g_off[ei[E + e]] + g_slot[e]] = ei[e];
    }
}

// ---------------- fp16 tensor-core GEMM: g_h16[M,:] = dis[row] * (A @ W) ------
// 64-row tiles, 128 threads (4 warps: 2M x 2N), warp tile 32x64, mma.m16n8k16.
// dis computed from g_cnt in the epilogue (no dependency on dis_k).
__global__ __launch_bounds__(128, 4)
void gemm_fp16_k(const float* __restrict__ Ax, const float* __restrict__ W,
                 int M, int use_ga)
{
    __shared__ __align__(16) __half2 As2[64][20];
    __shared__ __align__(16) __half2 Bs2[16][136];

    int tid  = threadIdx.x;
    int wid  = tid >> 5;
    int lane = tid & 31;
    int g    = lane >> 2;
    int tig  = lane & 3;
    int warp_m = wid & 1;
    int warp_n = wid >> 1;
    int row0 = blockIdx.x * 64;

    float acc[2][8][4];
#pragma unroll
    for (int mf = 0; mf < 2; mf++)
#pragma unroll
        for (int nf = 0; nf < 8; nf++)
#pragma unroll
            for (int i = 0; i < 4; i++) acc[mf][nf][i] = 0.f;

    for (int kb = 0; kb < 128; kb += 32) {
        if (use_ga) {
            // fp16 A: 64 rows x 32 halves = 256 16B chunks, 2 passes
            const __half* A16 = g_a16;
#pragma unroll
            for (int l = 0; l < 2; l++) {
                int idx = tid + l * 128;          // 0..255
                int r  = idx >> 2;
                int c8 = idx & 3;
                int gr = row0 + r;
                if (gr > M - 1) gr = M - 1;
                float4 raw = *(const float4*)(A16 + (size_t)gr * 128 + kb + c8 * 8);
                *(float4*)(&As2[r][c8 * 4]) = raw;
            }
        } else {
            // fp32 A: 64 rows x 8 float4 = 512 tasks, 4 passes
#pragma unroll
            for (int l = 0; l < 4; l++) {
                int idx = tid + l * 128;
                int r  = idx >> 3;
                int c4 = idx & 7;
                int gr = row0 + r;
                if (gr > M - 1) gr = M - 1;
                float4 v = *(const float4*)(Ax + (size_t)gr * 128 + kb + c4 * 4);
                As2[r][c4 * 2]     = __floats2half2_rn(v.x, v.y);
                As2[r][c4 * 2 + 1] = __floats2half2_rn(v.z, v.w);
            }
        }
        // W chunk: 16 k-pairs x 32 col-groups = 512 tasks, 4 passes
#pragma unroll
        for (int l = 0; l < 4; l++) {
            int idx = tid + l * 128;
            int r  = idx >> 5;
            int c4 = idx & 31;
            const float* w0 = W + (size_t)(kb + 2 * r) * 128 + c4 * 4;
            float4 v0 = *(const float4*)w0;
            float4 v1 = *(const float4*)(w0 + 128);
            __half2 p0 = __floats2half2_rn(v0.x, v1.x);
            __half2 p1 = __floats2half2_rn(v0.y, v1.y);
            __half2 p2 = __floats2half2_rn(v0.z, v1.z);
            __half2 p3 = __floats2half2_rn(v0.w, v1.w);
            __half2* d = &Bs2[r][c4 * 4];
            d[0] = p0; d[1] = p1; d[2] = p2; d[3] = p3;
        }
        __syncthreads();

#pragma unroll
        for (int ks = 0; ks < 2; ks++) {
            int k0 = ks * 8;
            unsigned a[2][4];
#pragma unroll
            for (int mf = 0; mf < 2; mf++) {
                int rb = warp_m * 32 + mf * 16 + g;
                a[mf][0] = *(unsigned*)&As2[rb][k0 + tig];
                a[mf][1] = *(unsigned*)&As2[rb + 8][k0 + tig];
                a[mf][2] = *(unsigned*)&As2[rb][k0 + tig + 4];
                a[mf][3] = *(unsigned*)&As2[rb + 8][k0 + tig + 4];
            }
            unsigned b[8][2];
#pragma unroll
            for (int nf = 0; nf < 8; nf++) {
                int cb = warp_n * 64 + nf * 8 + g;
                b[nf][0] = *(unsigned*)&Bs2[k0 + tig][cb];
                b[nf][1] = *(unsigned*)&Bs2[k0 + tig + 4][cb];
            }
#pragma unroll
            for (int mf = 0; mf < 2; mf++)
#pragma unroll
                for (int nf = 0; nf < 8; nf++) {
                    asm volatile(
                        "mma.sync.aligned.m16n8k16.row.col.f32.f16.f16.f32 "
                        "{%0,%1,%2,%3}, {%4,%5,%6,%7}, {%8,%9}, {%0,%1,%2,%3};"
                        : "+f"(acc[mf][nf][0]), "+f"(acc[mf][nf][1]),
                          "+f"(acc[mf][nf][2]), "+f"(acc[mf][nf][3])
                        : "r"(a[mf][0]), "r"(a[mf][1]), "r"(a[mf][2]), "r"(a[mf][3]),
                          "r"(b[nf][0]), "r"(b[nf][1]));
                }
        }
        __syncthreads();
    }

    // epilogue: scale by rsqrt(1+cnt[row]) computed inline, write fp16
#pragma unroll
    for (int mf = 0; mf < 2; mf++) {
        int rb = row0 + warp_m * 32 + mf * 16 + g;
        float d0 = (rb < M)     ? rsqrtf(1.0f + (float)g_cnt[rb])     : 0.f;
        float d1 = (rb + 8 < M) ? rsqrtf(1.0f + (float)g_cnt[rb + 8]) : 0.f;
#pragma unroll
        for (int nf = 0; nf < 8; nf++) {
            int col = warp_n * 64 + nf * 8 + tig * 2;
            if (rb < M) {
                __half2 v = __floats2half2_rn(d0 * acc[mf][nf][0], d0 * acc[mf][nf][1]);
                *(__half2*)(g_h16 + (size_t)rb * 128 + col) = v;
            }
            if (rb + 8 < M) {
                __half2 v = __floats2half2_rn(d1 * acc[mf][nf][2], d1 * acc[mf][nf][3]);
                *(__half2*)(g_h16 + (size_t)(rb + 8) * 128 + col) = v;
            }
        }
    }
}

// ---------------- aggregation: warp per node, pure gather+add ----------------
__global__ void agg128_k(const float* __restrict__ b, int M,
                         const float* __restrict__ W4)
{
    int w = (blockIdx.x * blockDim.x + threadIdx.x) >> 5;
    if (w >= M) return;
    int lane = threadIdx.x & 31;
    const __half* __restrict__ h = g_h16;
    int beg = g_off[w], end = g_off[w + 1];
    float dv = g_dis[w];

    float ax = 0.f, ay = 0.f, az = 0.f, aw = 0.f;
    int e = beg;
    for (; e < end && (e & 3); e++) {
        int s0 = g_csr[e];
        float4 h0 = h8_to_f4(((const float2*)(h + (size_t)s0 * 128))[lane]);
        ax += h0.x; ay += h0.y; az += h0.z; aw += h0.w;
    }
    for (; e + 8 <= end; e += 8) {
        int4 i0 = *(const int4*)(g_csr + e);
        int4 i1 = *(const int4*)(g_csr + e + 4);
        float2 r0 = ((const float2*)(h + (size_t)i0.x * 128))[lane];
        float2 r1 = ((const float2*)(h + (size_t)i0.y * 128))[lane];
        float2 r2 = ((const float2*)(h + (size_t)i0.z * 128))[lane];
        float2 r3 = ((const float2*)(h + (size_t)i0.w * 128))[lane];
        float2 r4 = ((const float2*)(h + (size_t)i1.x * 128))[lane];
        float2 r5 = ((const float2*)(h + (size_t)i1.y * 128))[lane];
        float2 r6 = ((const float2*)(h + (size_t)i1.z * 128))[lane];
        float2 r7 = ((const float2*)(h + (size_t)i1.w * 128))[lane];
        float4 p0 = pairsum_f4(r0, r1);
        float4 p1 = pairsum_f4(r2, r3);
        float4 p2 = pairsum_f4(r4, r5);
        float4 p3 = pairsum_f4(r6, r7);
        ax += (p0.x + p1.x) + (p2.x + p3.x);
        ay += (p0.y + p1.y) + (p2.y + p3.y);
        az += (p0.z + p1.z) + (p2.z + p3.z);
        aw += (p0.w + p1.w) + (p2.w + p3.w);
    }
    for (; e < end; e++) {
        int s0 = g_csr[e];
        float4 h0 = h8_to_f4(((const float2*)(h + (size_t)s0 * 128))[lane]);
        ax += h0.x; ay += h0.y; az += h0.z; aw += h0.w;
    }

    float4 hs = h8_to_f4(((const float2*)(h + (size_t)w * 128))[lane]);
    float4 bb = ((const float4*)b)[lane];
    float rx = fmaxf(dv * (ax + hs.x) + bb.x, 0.f);
    float ry = fmaxf(dv * (ay + hs.y) + bb.y, 0.f);
    float rz = fmaxf(dv * (az + hs.z) + bb.z, 0.f);
    float rw = fmaxf(dv * (aw + hs.w) + bb.w, 0.f);

    if (W4 == nullptr) {
        ((float2*)(g_a16 + (size_t)w * 128))[lane] = f4_to_h8(rx, ry, rz, rw);
    } else {
        float4 wv = ((const float4*)W4)[lane];
        float s = rx * wv.x + ry * wv.y + rz * wv.z + rw * wv.w;
#pragma unroll
        for (int o = 16; o; o >>= 1) s += __shfl_xor_sync(0xFFFFFFFFu, s, o);
        if (lane == 0) g_t[w] = dv * s;
    }
}

// warp per node: lanes gather edges in parallel, shfl reduce
__global__ void final_agg_k(const float* __restrict__ b4, float* __restrict__ out, int M)
{
    int w = (blockIdx.x * blockDim.x + threadIdx.x) >> 5;
    if (w >= M) return;
    int lane = threadIdx.x & 31;
    int beg = g_off[w], end = g_off[w + 1];
    float s = 0.f;
    for (int e = beg + lane; e < end; e += 32) s += g_t[g_csr[e]];
#pragma unroll
    for (int o = 16; o; o >>= 1) s += __shfl_xor_sync(0xFFFFFFFFu, s, o);
    if (lane == 0) out[w] = g_dis[w] * (s + g_t[w]) + b4[0];
}

// ---------------- launch ----------------
extern "C" void kernel_launch(void* const* d_in, const int* in_sizes, int n_in,
                              void* d_out, int out_size)
{
    const float* x  = (const float*)d_in[0];
    const int*   ei = (const int*)d_in[1];
    const float* W1 = (const float*)d_in[2]; const float* b1 = (const float*)d_in[3];
    const float* W2 = (const float*)d_in[4]; const float* b2 = (const float*)d_in[5];
    const float* W3 = (const float*)d_in[6]; const float* b3 = (const float*)d_in[7];
    const float* W4 = (const float*)d_in[8]; const float* b4 = (const float*)d_in[9];

    int N = in_sizes[0] / 128;   // 50000
    int E = in_sizes[1] / 2;     // 1600000
    float* out = (float*)d_out;

    int nb = (N + SCAN_B - 1) / SCAN_B;

    static cudaStream_t s2 = nullptr;
    static cudaEvent_t ev_fork, ev_cnt, ev_csr;
    if (s2 == nullptr) {
        cudaStreamCreateWithFlags(&s2, cudaStreamNonBlocking);
        cudaEventCreateWithFlags(&ev_fork, cudaEventDisableTiming);
        cudaEventCreateWithFlags(&ev_cnt,  cudaEventDisableTiming);
        cudaEventCreateWithFlags(&ev_csr,  cudaEventDisableTiming);
    }

    // fork: preprocessing on s2; cnt (for GEMM-1 epilogue) ready right after hist
    cudaEventRecord(ev_fork, 0);
    cudaStreamWaitEvent(s2, ev_fork, 0);
    zero_cnt_k <<<(N + 255) / 256, 256, 0, s2>>>(N);
    hist_dst_k <<<(E / 4 + 255) / 256, 256, 0, s2>>>(ei, E);
    cudaEventRecord(ev_cnt, s2);
    dis_k      <<<(N + 255) / 256, 256, 0, s2>>>(N);
    scan1_k    <<<nb, SCAN_B, 0, s2>>>(N);
    scan3_k    <<<(N + 255) / 256, 256, 0, s2>>>(N, nb);
    build_csr_k<<<(E / 4 + 255) / 256, 256, 0, s2>>>(ei, E);
    cudaEventRecord(ev_csr, s2);

    int gemm_blocks = (N + 63) / 64;            // 782
    int agg_blocks  = (N * 32 + 255) / 256;

    // GEMM-1 needs only g_cnt: overlaps dis/scan/build_csr on s2
    cudaStreamWaitEvent(0, ev_cnt, 0);
    gemm_fp16_k<<<gemm_blocks, 128>>>(x, W1, N, 0);
    cudaStreamWaitEvent(0, ev_csr, 0);
    agg128_k   <<<agg_blocks, 256>>>(b1, N, nullptr);

    gemm_fp16_k<<<gemm_blocks, 128>>>(x, W2, N, 1);
    agg128_k   <<<agg_blocks, 256>>>(b2, N, nullptr);

    gemm_fp16_k<<<gemm_blocks, 128>>>(x, W3, N, 1);
    agg128_k   <<<agg_blocks, 256>>>(b3, N, W4);

    final_agg_k<<<agg_blocks, 256>>>(b4, out, N);
}

// round 13
// speedup vs baseline: 1.0297x; 1.0297x over previous
#include <cuda_runtime.h>
#include <cuda_fp16.h>
#include <cstddef>

#define NN_MAX 50000
#define EE_MAX 1600000
#define SCAN_B 1024
#define NB_MAX 64

// -------- scratch (device globals; no allocation allowed) --------
__device__ __align__(16) float  g_dis[NN_MAX];
__device__ int    g_cnt[NN_MAX];
__device__ int    g_off[NN_MAX + 1];
__device__ int    g_sl[NN_MAX];
__device__ int    g_bsum[NB_MAX];
__device__ __align__(16) int g_slot[EE_MAX];
__device__ __align__(16) int g_csr[EE_MAX];
__device__ __align__(16) __half g_h16[(size_t)NN_MAX * 128];  // post-GEMM, pre-scaled
__device__ __align__(16) __half g_a16[(size_t)NN_MAX * 128];  // post-agg activations
__device__ float  g_t[NN_MAX];

// ---------------- helpers ----------------
__device__ __forceinline__ float4 h8_to_f4(float2 raw) {
    __half2 ha = *reinterpret_cast<__half2*>(&raw.x);
    __half2 hb = *reinterpret_cast<__half2*>(&raw.y);
    float2 fa = __half22float2(ha), fb = __half22float2(hb);
    return make_float4(fa.x, fa.y, fb.x, fb.y);
}
__device__ __forceinline__ float2 f4_to_h8(float x, float y, float z, float w) {
    __half2 h0 = __floats2half2_rn(x, y), h1 = __floats2half2_rn(z, w);
    float2 o;
    o.x = *reinterpret_cast<float*>(&h0);
    o.y = *reinterpret_cast<float*>(&h1);
    return o;
}
__device__ __forceinline__ float4 pairsum_f4(float2 ra, float2 rb) {
    __half2 alo = *reinterpret_cast<__half2*>(&ra.x);
    __half2 ahi = *reinterpret_cast<__half2*>(&ra.y);
    __half2 blo = *reinterpret_cast<__half2*>(&rb.x);
    __half2 bhi = *reinterpret_cast<__half2*>(&rb.y);
    __half2 slo = __hadd2(alo, blo);
    __half2 shi = __hadd2(ahi, bhi);
    float2 fa = __half22float2(slo), fb = __half22float2(shi);
    return make_float4(fa.x, fa.y, fb.x, fb.y);
}

// ---------------- graph preprocessing ----------------
__global__ void zero_cnt_k(int n) {
    int i = blockIdx.x * blockDim.x + threadIdx.x;
    if (i < n) g_cnt[i] = 0;
}

__global__ void hist_dst_k(const int* __restrict__ ei, int E) {
    int t = blockIdx.x * blockDim.x + threadIdx.x;
    int e = t * 4;
    if (e + 3 < E) {
        int4 d = *(const int4*)(ei + E + e);
        int p0 = atomicAdd(&g_cnt[d.x], 1);
        int p1 = atomicAdd(&g_cnt[d.y], 1);
        int p2 = atomicAdd(&g_cnt[d.z], 1);
        int p3 = atomicAdd(&g_cnt[d.w], 1);
        *(int4*)(g_slot + e) = make_int4(p0, p1, p2, p3);
    } else {
        for (; e < E; e++) g_slot[e] = atomicAdd(&g_cnt[ei[E + e]], 1);
    }
}

// dis for agg kernels (off critical path; GEMM computes rsqrt from g_cnt itself)
__global__ void dis_k(int n) {
    int i = blockIdx.x * blockDim.x + threadIdx.x;
    if (i < n) g_dis[i] = rsqrtf(1.0f + (float)g_cnt[i]);
}

__global__ void scan1_k(int n) {
    __shared__ int sh[SCAN_B];
    int t = threadIdx.x;
    int i = blockIdx.x * SCAN_B + t;
    int v = (i < n) ? g_cnt[i] : 0;
    sh[t] = v;
    __syncthreads();
    for (int d = 1; d < SCAN_B; d <<= 1) {
        int u = (t >= d) ? sh[t - d] : 0;
        __syncthreads();
        sh[t] += u;
        __syncthreads();
    }
    if (i < n) g_sl[i] = sh[t] - v;
    if (t == SCAN_B - 1) g_bsum[blockIdx.x] = sh[t];
}

__global__ void scan3_k(int n, int nb) {
    __shared__ int sh[NB_MAX];
    int t = threadIdx.x;
    if (t < NB_MAX) sh[t] = (t < nb) ? g_bsum[t] : 0;
    __syncthreads();
    for (int d = 1; d < NB_MAX; d <<= 1) {
        int u = (t < NB_MAX && t >= d) ? sh[t - d] : 0;
        __syncthreads();
        if (t < NB_MAX) sh[t] += u;
        __syncthreads();
    }
    int i = blockIdx.x * blockDim.x + t;
    if (i >= n) return;
    int bidx = i >> 10;
    int boff = (bidx > 0) ? sh[bidx - 1] : 0;
    int off = g_sl[i] + boff;
    g_off[i] = off;
    if (i == n - 1) g_off[n] = off + g_cnt[i];
}

__global__ void build_csr_k(const int* __restrict__ ei, int E) {
    int t = blockIdx.x * blockDim.x + threadIdx.x;
    int e = t * 4;
    if (e + 3 < E) {
        int4 s  = *(const int4*)(ei + e);
        int4 d  = *(const int4*)(ei + E + e);
        int4 sl = *(const int4*)(g_slot + e);
        g_csr[g_off[d.x] + sl.x] = s.x;
        g_csr[g_off[d.y] + sl.y] = s.y;
        g_csr[g_off[d.z] + sl.z] = s.z;
        g_csr[g_off[d.w] + sl.w] = s.w;
    } else {
        for (; e < E; e++) g_csr[g_off[ei[E + e]] + g_slot[e]] = ei[e];
    }
}

// ---------------- fp16 tensor-core GEMM: g_h16[M,:] = dis[row] * (A @ W) ------
// 128-row tiles, 256 threads (8 warps: 4M x 2N), warp tile 32x64, mma.m16n8k16.
// K chunked by 64 (2 chunks, 4 syncs total). dis computed inline from g_cnt.
// As2: half2 [128][36] (4g mod 32 distinct -> conflict-free frag reads)
// Bs2: half2 [32][136] (8tig+g covers all banks)
__global__ __launch_bounds__(256, 2)
void gemm_fp16_k(const float* __restrict__ Ax, const float* __restrict__ W,
                 int M, int use_ga)
{
    __shared__ __align__(16) __half2 As2[128][36];
    __shared__ __align__(16) __half2 Bs2[32][136];

    int tid  = threadIdx.x;
    int wid  = tid >> 5;
    int lane = tid & 31;
    int g    = lane >> 2;
    int tig  = lane & 3;
    int warp_m = wid & 3;
    int warp_n = wid >> 2;
    int row0 = blockIdx.x * 128;

    float acc[2][8][4];
#pragma unroll
    for (int mf = 0; mf < 2; mf++)
#pragma unroll
        for (int nf = 0; nf < 8; nf++)
#pragma unroll
            for (int i = 0; i < 4; i++) acc[mf][nf][i] = 0.f;

    for (int kb = 0; kb < 128; kb += 64) {
        if (use_ga) {
            // fp16 A: 128 rows x 64 halves = 1024 16B chunks, 4 passes
            const __half* A16 = g_a16;
#pragma unroll
            for (int l = 0; l < 4; l++) {
                int idx = tid + l * 256;          // 0..1023
                int r  = idx >> 3;
                int c8 = idx & 7;                 // 8-half group (8 per row)
                int gr = row0 + r;
                if (gr > M - 1) gr = M - 1;
                float4 raw = *(const float4*)(A16 + (size_t)gr * 128 + kb + c8 * 8);
                *(float4*)(&As2[r][c8 * 4]) = raw;
            }
        } else {
            // fp32 A: 128 rows x 16 float4 = 2048 tasks, 8 passes
#pragma unroll
            for (int l = 0; l < 8; l++) {
                int idx = tid + l * 256;
                int r  = idx >> 4;
                int c4 = idx & 15;
                int gr = row0 + r;
                if (gr > M - 1) gr = M - 1;
                float4 v = *(const float4*)(Ax + (size_t)gr * 128 + kb + c4 * 4);
                As2[r][c4 * 2]     = __floats2half2_rn(v.x, v.y);
                As2[r][c4 * 2 + 1] = __floats2half2_rn(v.z, v.w);
            }
        }
        // W chunk: 32 k-pairs x 32 col-groups = 1024 tasks, 4 passes
#pragma unroll
        for (int l = 0; l < 4; l++) {
            int idx = tid + l * 256;
            int r  = idx >> 5;                    // k-pair 0..31
            int c4 = idx & 31;
            const float* w0 = W + (size_t)(kb + 2 * r) * 128 + c4 * 4;
            float4 v0 = *(const float4*)w0;
            float4 v1 = *(const float4*)(w0 + 128);
            __half2 p0 = __floats2half2_rn(v0.x, v1.x);
            __half2 p1 = __floats2half2_rn(v0.y, v1.y);
            __half2 p2 = __floats2half2_rn(v0.z, v1.z);
            __half2 p3 = __floats2half2_rn(v0.w, v1.w);
            __half2* d = &Bs2[r][c4 * 4];
            d[0] = p0; d[1] = p1; d[2] = p2; d[3] = p3;
        }
        __syncthreads();

#pragma unroll
        for (int ks = 0; ks < 4; ks++) {          // four k16 steps per chunk
            int k0 = ks * 8;                      // in half2 units
            unsigned a[2][4];
#pragma unroll
            for (int mf = 0; mf < 2; mf++) {
                int rb = warp_m * 32 + mf * 16 + g;
                a[mf][0] = *(unsigned*)&As2[rb][k0 + tig];
                a[mf][1] = *(unsigned*)&As2[rb + 8][k0 + tig];
                a[mf][2] = *(unsigned*)&As2[rb][k0 + tig + 4];
                a[mf][3] = *(unsigned*)&As2[rb + 8][k0 + tig + 4];
            }
            unsigned b[8][2];
#pragma unroll
            for (int nf = 0; nf < 8; nf++) {
                int cb = warp_n * 64 + nf * 8 + g;
                b[nf][0] = *(unsigned*)&Bs2[k0 + tig][cb];
                b[nf][1] = *(unsigned*)&Bs2[k0 + tig + 4][cb];
            }
#pragma unroll
            for (int mf = 0; mf < 2; mf++)
#pragma unroll
                for (int nf = 0; nf < 8; nf++) {
                    asm volatile(
                        "mma.sync.aligned.m16n8k16.row.col.f32.f16.f16.f32 "
                        "{%0,%1,%2,%3}, {%4,%5,%6,%7}, {%8,%9}, {%0,%1,%2,%3};"
                        : "+f"(acc[mf][nf][0]), "+f"(acc[mf][nf][1]),
                          "+f"(acc[mf][nf][2]), "+f"(acc[mf][nf][3])
                        : "r"(a[mf][0]), "r"(a[mf][1]), "r"(a[mf][2]), "r"(a[mf][3]),
                          "r"(b[nf][0]), "r"(b[nf][1]));
                }
        }
        __syncthreads();
    }

    // epilogue: scale by rsqrt(1+cnt[row]) computed inline, write fp16
#pragma unroll
    for (int mf = 0; mf < 2; mf++) {
        int rb = row0 + warp_m * 32 + mf * 16 + g;
        float d0 = (rb < M)     ? rsqrtf(1.0f + (float)g_cnt[rb])     : 0.f;
        float d1 = (rb + 8 < M) ? rsqrtf(1.0f + (float)g_cnt[rb + 8]) : 0.f;
#pragma unroll
        for (int nf = 0; nf < 8; nf++) {
            int col = warp_n * 64 + nf * 8 + tig * 2;
            if (rb < M) {
                __half2 v = __floats2half2_rn(d0 * acc[mf][nf][0], d0 * acc[mf][nf][1]);
                *(__half2*)(g_h16 + (size_t)rb * 128 + col) = v;
            }
            if (rb + 8 < M) {
                __half2 v = __floats2half2_rn(d1 * acc[mf][nf][2], d1 * acc[mf][nf][3]);
                *(__half2*)(g_h16 + (size_t)(rb + 8) * 128 + col) = v;
            }
        }
    }
}

// ---------------- aggregation: warp per node, pure gather+add ----------------
__global__ void agg128_k(const float* __restrict__ b, int M,
                         const float* __restrict__ W4)
{
    int w = (blockIdx.x * blockDim.x + threadIdx.x) >> 5;
    if (w >= M) return;
    int lane = threadIdx.x & 31;
    const __half* __restrict__ h = g_h16;
    int beg = g_off[w], end = g_off[w + 1];
    float dv = g_dis[w];

    float ax = 0.f, ay = 0.f, az = 0.f, aw = 0.f;
    int e = beg;
    for (; e < end && (e & 3); e++) {
        int s0 = g_csr[e];
        float4 h0 = h8_to_f4(((const float2*)(h + (size_t)s0 * 128))[lane]);
        ax += h0.x; ay += h0.y; az += h0.z; aw += h0.w;
    }
    for (; e + 8 <= end; e += 8) {
        int4 i0 = *(const int4*)(g_csr + e);
        int4 i1 = *(const int4*)(g_csr + e + 4);
        float2 r0 = ((const float2*)(h + (size_t)i0.x * 128))[lane];
        float2 r1 = ((const float2*)(h + (size_t)i0.y * 128))[lane];
        float2 r2 = ((const float2*)(h + (size_t)i0.z * 128))[lane];
        float2 r3 = ((const float2*)(h + (size_t)i0.w * 128))[lane];
        float2 r4 = ((const float2*)(h + (size_t)i1.x * 128))[lane];
        float2 r5 = ((const float2*)(h + (size_t)i1.y * 128))[lane];
        float2 r6 = ((const float2*)(h + (size_t)i1.z * 128))[lane];
        float2 r7 = ((const float2*)(h + (size_t)i1.w * 128))[lane];
        float4 p0 = pairsum_f4(r0, r1);
        float4 p1 = pairsum_f4(r2, r3);
        float4 p2 = pairsum_f4(r4, r5);
        float4 p3 = pairsum_f4(r6, r7);
        ax += (p0.x + p1.x) + (p2.x + p3.x);
        ay += (p0.y + p1.y) + (p2.y + p3.y);
        az += (p0.z + p1.z) + (p2.z + p3.z);
        aw += (p0.w + p1.w) + (p2.w + p3.w);
    }
    for (; e < end; e++) {
        int s0 = g_csr[e];
        float4 h0 = h8_to_f4(((const float2*)(h + (size_t)s0 * 128))[lane]);
        ax += h0.x; ay += h0.y; az += h0.z; aw += h0.w;
    }

    float4 hs = h8_to_f4(((const float2*)(h + (size_t)w * 128))[lane]);
    float4 bb = ((const float4*)b)[lane];
    float rx = fmaxf(dv * (ax + hs.x) + bb.x, 0.f);
    float ry = fmaxf(dv * (ay + hs.y) + bb.y, 0.f);
    float rz = fmaxf(dv * (az + hs.z) + bb.z, 0.f);
    float rw = fmaxf(dv * (aw + hs.w) + bb.w, 0.f);

    if (W4 == nullptr) {
        ((float2*)(g_a16 + (size_t)w * 128))[lane] = f4_to_h8(rx, ry, rz, rw);
    } else {
        float4 wv = ((const float4*)W4)[lane];
        float s = rx * wv.x + ry * wv.y + rz * wv.z + rw * wv.w;
#pragma unroll
        for (int o = 16; o; o >>= 1) s += __shfl_xor_sync(0xFFFFFFFFu, s, o);
        if (lane == 0) g_t[w] = dv * s;
    }
}

// warp per node: lanes gather edges in parallel, shfl reduce
__global__ void final_agg_k(const float* __restrict__ b4, float* __restrict__ out, int M)
{
    int w = (blockIdx.x * blockDim.x + threadIdx.x) >> 5;
    if (w >= M) return;
    int lane = threadIdx.x & 31;
    int beg = g_off[w], end = g_off[w + 1];
    float s = 0.f;
    for (int e = beg + lane; e < end; e += 32) s += g_t[g_csr[e]];
#pragma unroll
    for (int o = 16; o; o >>= 1) s += __shfl_xor_sync(0xFFFFFFFFu, s, o);
    if (lane == 0) out[w] = g_dis[w] * (s + g_t[w]) + b4[0];
}

// ---------------- launch ----------------
extern "C" void kernel_launch(void* const* d_in, const int* in_sizes, int n_in,
                              void* d_out, int out_size)
{
    const float* x  = (const float*)d_in[0];
    const int*   ei = (const int*)d_in[1];
    const float* W1 = (const float*)d_in[2]; const float* b1 = (const float*)d_in[3];
    const float* W2 = (const float*)d_in[4]; const float* b2 = (const float*)d_in[5];
    const float* W3 = (const float*)d_in[6]; const float* b3 = (const float*)d_in[7];
    const float* W4 = (const float*)d_in[8]; const float* b4 = (const float*)d_in[9];

    int N = in_sizes[0] / 128;   // 50000
    int E = in_sizes[1] / 2;     // 1600000
    float* out = (float*)d_out;

    int nb = (N + SCAN_B - 1) / SCAN_B;

    static cudaStream_t s2 = nullptr;
    static cudaEvent_t ev_fork, ev_cnt, ev_csr;
    if (s2 == nullptr) {
        cudaStreamCreateWithFlags(&s2, cudaStreamNonBlocking);
        cudaEventCreateWithFlags(&ev_fork, cudaEventDisableTiming);
        cudaEventCreateWithFlags(&ev_cnt,  cudaEventDisableTiming);
        cudaEventCreateWithFlags(&ev_csr,  cudaEventDisableTiming);
    }

    // fork: preprocessing on s2; cnt (for GEMM-1 epilogue) ready right after hist
    cudaEventRecord(ev_fork, 0);
    cudaStreamWaitEvent(s2, ev_fork, 0);
    zero_cnt_k <<<(N + 255) / 256, 256, 0, s2>>>(N);
    hist_dst_k <<<(E / 4 + 255) / 256, 256, 0, s2>>>(ei, E);
    cudaEventRecord(ev_cnt, s2);
    dis_k      <<<(N + 255) / 256, 256, 0, s2>>>(N);
    scan1_k    <<<nb, SCAN_B, 0, s2>>>(N);
    scan3_k    <<<(N + 255) / 256, 256, 0, s2>>>(N, nb);
    build_csr_k<<<(E / 4 + 255) / 256, 256, 0, s2>>>(ei, E);
    cudaEventRecord(ev_csr, s2);

    int gemm_blocks = (N + 127) / 128;          // 391
    int agg_blocks  = (N * 32 + 255) / 256;

    // GEMM-1 needs only g_cnt: overlaps dis/scan/build_csr on s2
    cudaStreamWaitEvent(0, ev_cnt, 0);
    gemm_fp16_k<<<gemm_blocks, 256>>>(x, W1, N, 0);
    cudaStreamWaitEvent(0, ev_csr, 0);
    agg128_k   <<<agg_blocks, 256>>>(b1, N, nullptr);

    gemm_fp16_k<<<gemm_blocks, 256>>>(x, W2, N, 1);
    agg128_k   <<<agg_blocks, 256>>>(b2, N, nullptr);

    gemm_fp16_k<<<gemm_blocks, 256>>>(x, W3, N, 1);
    agg128_k   <<<agg_blocks, 256>>>(b3, N, W4);

    final_agg_k<<<agg_blocks, 256>>>(b4, out, N);
}